// round 4
// baseline (speedup 1.0000x reference)
#include <cuda_runtime.h>
#include <math.h>

// TropicalAffine: LayerNorm -> max-plus matmul -> max(., bias)
// Exact candidate-pruned tropical matmul.
//   Select S_b = {k : xn[b,k] > TAU}; est over S_b; certify with
//   excluded <= TAU + colmax_W[i]; rare exact per-element fallback.
// R3: compacted sorted candidate lists (branch-free unroll-2 consumer),
//     50% occupancy, light alignment barriers for cross-warp L1 reuse.

#define Bn 4096
#define Fn 1024
#define Gq 16
#define CAP 256
#define TAU 1.00f
#define LN_EPS 1e-5f

__device__ float  g_xn[Bn * Fn];          // layernorm output (fallback only)
__device__ float2 g_cand[Bn * CAP];       // (xn value, k*(Fn/4) as int bits)
__device__ int    g_cnt[Bn];              // padded candidate count
__device__ float  g_cmax[Fn];             // column max of W
__device__ float  g_part[8 * Fn];         // colmax partials

// ---------------------------------------------------------------------------
// Kernel 1: LayerNorm + order-preserving candidate compaction.
// One block (256 thr) per row; thread tid owns k = 4*tid..4*tid+3.
// ---------------------------------------------------------------------------
__global__ __launch_bounds__(256) void ln_select_kernel(
    const float* __restrict__ x,
    const float* __restrict__ gamma,
    const float* __restrict__ beta)
{
    const int b    = blockIdx.x;
    const int tid  = threadIdx.x;
    const int warp = tid >> 5, lane = tid & 31;

    __shared__ float ws[8], wq[8];
    __shared__ float s_mu, s_rs;
    __shared__ int   wsum[8], wbase[8], s_tot;

    float4 v = ((const float4*)(x + (size_t)b * Fn))[tid];
    float s = v.x + v.y + v.z + v.w;
    float q = v.x * v.x + v.y * v.y + v.z * v.z + v.w * v.w;

    #pragma unroll
    for (int o = 16; o > 0; o >>= 1) {
        s += __shfl_xor_sync(0xFFFFFFFFu, s, o);
        q += __shfl_xor_sync(0xFFFFFFFFu, q, o);
    }
    if (lane == 0) { ws[warp] = s; wq[warp] = q; }
    __syncthreads();

    if (tid == 0) {
        float ts = 0.f, tq = 0.f;
        #pragma unroll
        for (int i = 0; i < 8; i++) { ts += ws[i]; tq += wq[i]; }
        float mu  = ts * (1.0f / Fn);
        float var = tq * (1.0f / Fn) - mu * mu;
        s_mu = mu;
        s_rs = rsqrtf(var + LN_EPS);
    }
    __syncthreads();

    const float mu = s_mu, rs = s_rs;
    float4 g  = ((const float4*)gamma)[tid];
    float4 be = ((const float4*)beta)[tid];

    float xn[4];
    xn[0] = (v.x - mu) * rs * g.x + be.x;
    xn[1] = (v.y - mu) * rs * g.y + be.y;
    xn[2] = (v.z - mu) * rs * g.z + be.z;
    xn[3] = (v.w - mu) * rs * g.w + be.w;

    ((float4*)(g_xn + (size_t)b * Fn))[tid] =
        make_float4(xn[0], xn[1], xn[2], xn[3]);

    // Flags + per-thread count.
    unsigned f = 0u;
    #pragma unroll
    for (int j = 0; j < 4; j++)
        if (xn[j] > TAU) f |= (1u << j);
    int pcnt = __popc(f);

    // Warp inclusive scan -> exclusive offset.
    int inc = pcnt;
    #pragma unroll
    for (int o = 1; o < 32; o <<= 1) {
        int t = __shfl_up_sync(0xFFFFFFFFu, inc, o);
        if (lane >= o) inc += t;
    }
    int exclw = inc - pcnt;
    if (lane == 31) wsum[warp] = inc;
    __syncthreads();
    if (tid == 0) {
        int run = 0;
        #pragma unroll
        for (int i = 0; i < 8; i++) { wbase[i] = run; run += wsum[i]; }
        s_tot = run;
    }
    __syncthreads();

    float2* cand = g_cand + (size_t)b * CAP;
    int pos = wbase[warp] + exclw;
    const int kb = tid * 4;
    #pragma unroll
    for (int j = 0; j < 4; j++) {
        if ((f >> j) & 1) {
            if (pos < CAP)
                cand[pos] = make_float2(xn[j],
                                        __int_as_float((kb + j) * (Fn / 4)));
            pos++;
        }
    }

    const int tot  = s_tot;
    const int totp = (tot + 7) & ~7;
    if (totp > CAP) {                 // statistically impossible; safe fallback
        if (tid == 0) g_cnt[b] = 0;
    } else {
        if (tid < totp - tot)
            cand[tot + tid] = make_float2(-INFINITY, __int_as_float(0));
        if (tid == 0) g_cnt[b] = totp;
    }
}

// ---------------------------------------------------------------------------
// Kernel 2a/2b: column max of W.
// ---------------------------------------------------------------------------
__global__ __launch_bounds__(256) void colmax_a(const float* __restrict__ W)
{
    const int kc = blockIdx.x >> 2;
    const int i  = (blockIdx.x & 3) * 256 + threadIdx.x;
    float m = -INFINITY;
    const int k0 = kc * 128;
    #pragma unroll 8
    for (int k = k0; k < k0 + 128; k++)
        m = fmaxf(m, W[(size_t)k * Fn + i]);
    g_part[kc * Fn + i] = m;
}

__global__ __launch_bounds__(256) void colmax_b()
{
    const int i = blockIdx.x * 256 + threadIdx.x;
    float m = -INFINITY;
    #pragma unroll
    for (int j = 0; j < 8; j++)
        m = fmaxf(m, g_part[j * Fn + i]);
    g_cmax[i] = m;
}

// ---------------------------------------------------------------------------
// Kernel 3: pruned tropical matmul. 16 rows/block, warp = row.
// Thread owns 32 cols: i = c*128 + lane*4, c = 0..7. Branch-free unroll-2
// candidate loop; barrier every 32 entries keeps warps in one L1 window.
// ---------------------------------------------------------------------------
__global__ __launch_bounds__(512, 2) void tropical_kernel(
    const float* __restrict__ W,
    const float* __restrict__ bias,
    float* __restrict__ out)
{
    const int g    = blockIdx.x;
    const int tid  = threadIdx.x;
    const int wid  = tid >> 5;
    const int lane = tid & 31;
    const int b    = g * Gq + wid;

    __shared__ float2 s_cand[Gq][CAP];   // 32 KB
    __shared__ int    s_cnt[Gq];
    __shared__ int    s_max;

    const int cnt = g_cnt[b];
    for (int j = lane; j < cnt; j += 32)
        s_cand[wid][j] = g_cand[(size_t)b * CAP + j];
    if (lane == 0) s_cnt[wid] = cnt;
    __syncthreads();
    if (tid == 0) {
        int m = 0;
        #pragma unroll
        for (int i = 0; i < Gq; i++) m = max(m, s_cnt[i]);
        s_max = m;
    }
    __syncthreads();
    const int smax = s_max;

    float a[8][4];
    #pragma unroll
    for (int c = 0; c < 8; c++)
        #pragma unroll
        for (int e = 0; e < 4; e++) a[c][e] = -INFINITY;

    const float4* W4 = (const float4*)W;

    for (int s0 = 0; s0 < smax; s0 += 32) {
        const int jend = min(s0 + 32, cnt);
        for (int j = s0; j < jend; j += 2) {
            float2 e0 = s_cand[wid][j];
            float2 e1 = s_cand[wid][j + 1];
            const float4* p0 = W4 + __float_as_int(e0.y) + lane;
            const float4* p1 = W4 + __float_as_int(e1.y) + lane;
            const float s0v = e0.x, s1v = e1.x;
            #pragma unroll
            for (int c = 0; c < 8; c++) {
                float4 v0 = p0[c * 32];
                float4 v1 = p1[c * 32];
                a[c][0] = fmaxf(a[c][0], s0v + v0.x);
                a[c][1] = fmaxf(a[c][1], s0v + v0.y);
                a[c][2] = fmaxf(a[c][2], s0v + v0.z);
                a[c][3] = fmaxf(a[c][3], s0v + v0.w);
                a[c][0] = fmaxf(a[c][0], s1v + v1.x);
                a[c][1] = fmaxf(a[c][1], s1v + v1.y);
                a[c][2] = fmaxf(a[c][2], s1v + v1.z);
                a[c][3] = fmaxf(a[c][3], s1v + v1.w);
            }
        }
        __syncthreads();
    }

    // Certificate + (never-fires) exact fallback + tropical bias + store.
    const float* xrow = g_xn + (size_t)b * Fn;
    float* orow = out + (size_t)b * Fn;
    #pragma unroll
    for (int c = 0; c < 8; c++) {
        const int i = c * 128 + lane * 4;
        float4 cm = *(const float4*)(g_cmax + i);
        const float th[4] = {TAU + cm.x, TAU + cm.y, TAU + cm.z, TAU + cm.w};
        #pragma unroll
        for (int e = 0; e < 4; e++) {
            if (a[c][e] < th[e]) {
                float mfull = -INFINITY;
                const float* wc = W + (i + e);
                for (int k = 0; k < Fn; k++)
                    mfull = fmaxf(mfull, xrow[k] + wc[(size_t)k * Fn]);
                a[c][e] = mfull;
            }
        }
        float4 bb = *(const float4*)(bias + i);
        *(float4*)(orow + i) = make_float4(fmaxf(a[c][0], bb.x),
                                           fmaxf(a[c][1], bb.y),
                                           fmaxf(a[c][2], bb.z),
                                           fmaxf(a[c][3], bb.w));
    }
}

// ---------------------------------------------------------------------------
extern "C" void kernel_launch(void* const* d_in, const int* in_sizes, int n_in,
                              void* d_out, int out_size)
{
    const float* x     = (const float*)d_in[0];
    const float* W     = (const float*)d_in[1];
    const float* bvec  = (const float*)d_in[2];
    const float* gamma = (const float*)d_in[3];
    const float* beta  = (const float*)d_in[4];
    float* out = (float*)d_out;

    ln_select_kernel<<<Bn, 256>>>(x, gamma, beta);
    colmax_a<<<32, 256>>>(W);
    colmax_b<<<4, 256>>>();
    tropical_kernel<<<Bn / Gq, 512>>>(W, bvec, out);
}

// round 5
// speedup vs baseline: 1.0587x; 1.0587x over previous
#include <cuda_runtime.h>
#include <math.h>

// TropicalAffine: LayerNorm -> max-plus matmul -> max(., bias)
// Exact candidate-pruned tropical matmul.
//   S_b = {k : xn[b,k] > TAU}; est over S_b; certify exactness via
//   excluded <= TAU + colmax_W[i]; exact per-element fallback (never fires
//   at TAU=1.0, P~4e-9).
// R4: 16 accumulators/thread (2 warps per row, 8 rows/block), 42-reg cap,
//     3 blocks/SM (75% occ). Compacted k-sorted candidate lists, branch-free
//     inner loop, 32-entry windows + barrier for cross-warp L1 reuse.

#define Bn 4096
#define Fn 1024
#define RPB 8
#define CAP 256
#define TAU 1.00f
#define LN_EPS 1e-5f

__device__ float  g_xn[Bn * Fn];          // layernorm output (fallback only)
__device__ float2 g_cand[Bn * CAP];       // (xn value, k*(Fn/4) as int bits)
__device__ int    g_cnt[Bn];              // padded candidate count
__device__ float  g_cmax[Fn];             // column max of W
__device__ float  g_part[8 * Fn];         // colmax partials

// ---------------------------------------------------------------------------
// Kernel 1: LayerNorm + order-preserving candidate compaction.
// One block (256 thr) per row; thread tid owns k = 4*tid..4*tid+3.
// ---------------------------------------------------------------------------
__global__ __launch_bounds__(256) void ln_select_kernel(
    const float* __restrict__ x,
    const float* __restrict__ gamma,
    const float* __restrict__ beta)
{
    const int b    = blockIdx.x;
    const int tid  = threadIdx.x;
    const int warp = tid >> 5, lane = tid & 31;

    __shared__ float ws[8], wq[8];
    __shared__ float s_mu, s_rs;
    __shared__ int   wsum[8], wbase[8], s_tot;

    float4 v = ((const float4*)(x + (size_t)b * Fn))[tid];
    float s = v.x + v.y + v.z + v.w;
    float q = v.x * v.x + v.y * v.y + v.z * v.z + v.w * v.w;

    #pragma unroll
    for (int o = 16; o > 0; o >>= 1) {
        s += __shfl_xor_sync(0xFFFFFFFFu, s, o);
        q += __shfl_xor_sync(0xFFFFFFFFu, q, o);
    }
    if (lane == 0) { ws[warp] = s; wq[warp] = q; }
    __syncthreads();

    if (tid == 0) {
        float ts = 0.f, tq = 0.f;
        #pragma unroll
        for (int i = 0; i < 8; i++) { ts += ws[i]; tq += wq[i]; }
        float mu  = ts * (1.0f / Fn);
        float var = tq * (1.0f / Fn) - mu * mu;
        s_mu = mu;
        s_rs = rsqrtf(var + LN_EPS);
    }
    __syncthreads();

    const float mu = s_mu, rs = s_rs;
    float4 g  = ((const float4*)gamma)[tid];
    float4 be = ((const float4*)beta)[tid];

    float xn[4];
    xn[0] = (v.x - mu) * rs * g.x + be.x;
    xn[1] = (v.y - mu) * rs * g.y + be.y;
    xn[2] = (v.z - mu) * rs * g.z + be.z;
    xn[3] = (v.w - mu) * rs * g.w + be.w;

    ((float4*)(g_xn + (size_t)b * Fn))[tid] =
        make_float4(xn[0], xn[1], xn[2], xn[3]);

    unsigned f = 0u;
    #pragma unroll
    for (int j = 0; j < 4; j++)
        if (xn[j] > TAU) f |= (1u << j);
    int pcnt = __popc(f);

    int inc = pcnt;
    #pragma unroll
    for (int o = 1; o < 32; o <<= 1) {
        int t = __shfl_up_sync(0xFFFFFFFFu, inc, o);
        if (lane >= o) inc += t;
    }
    int exclw = inc - pcnt;
    if (lane == 31) wsum[warp] = inc;
    __syncthreads();
    if (tid == 0) {
        int run = 0;
        #pragma unroll
        for (int i = 0; i < 8; i++) { wbase[i] = run; run += wsum[i]; }
        s_tot = run;
    }
    __syncthreads();

    float2* cand = g_cand + (size_t)b * CAP;
    int pos = wbase[warp] + exclw;
    const int kb = tid * 4;
    #pragma unroll
    for (int j = 0; j < 4; j++) {
        if ((f >> j) & 1) {
            if (pos < CAP)
                cand[pos] = make_float2(xn[j],
                                        __int_as_float((kb + j) * (Fn / 4)));
            pos++;
        }
    }

    const int tot  = s_tot;
    const int totp = (tot + 3) & ~3;
    if (totp > CAP) {                 // statistically impossible; safe fallback
        if (tid == 0) g_cnt[b] = 0;
    } else {
        if (tid < totp - tot)
            cand[tot + tid] = make_float2(-INFINITY, __int_as_float(0));
        if (tid == 0) g_cnt[b] = totp;
    }
}

// ---------------------------------------------------------------------------
// Kernel 2a/2b: column max of W.
// ---------------------------------------------------------------------------
__global__ __launch_bounds__(256) void colmax_a(const float* __restrict__ W)
{
    const int kc = blockIdx.x >> 2;
    const int i  = (blockIdx.x & 3) * 256 + threadIdx.x;
    float m = -INFINITY;
    const int k0 = kc * 128;
    #pragma unroll 8
    for (int k = k0; k < k0 + 128; k++)
        m = fmaxf(m, W[(size_t)k * Fn + i]);
    g_part[kc * Fn + i] = m;
}

__global__ __launch_bounds__(256) void colmax_b()
{
    const int i = blockIdx.x * 256 + threadIdx.x;
    float m = -INFINITY;
    #pragma unroll
    for (int j = 0; j < 8; j++)
        m = fmaxf(m, g_part[j * Fn + i]);
    g_cmax[i] = m;
}

// ---------------------------------------------------------------------------
// Kernel 3: pruned tropical matmul.
// 8 rows/block, 2 warps per row (warp w: row = w>>1, column half = w&1).
// Thread owns 16 cols: i = half*512 + c*128 + lane*4, c = 0..3.
// 16 register accumulators, ~40 live regs -> 3 blocks/SM.
// ---------------------------------------------------------------------------
__global__ __launch_bounds__(512, 3) void tropical_kernel(
    const float* __restrict__ W,
    const float* __restrict__ bias,
    float* __restrict__ out)
{
    const int g    = blockIdx.x;
    const int tid  = threadIdx.x;
    const int wid  = tid >> 5;
    const int lane = tid & 31;
    const int r    = wid >> 1;          // row within block
    const int h    = wid & 1;           // column half
    const int b    = g * RPB + r;

    __shared__ float2 s_cand[RPB][CAP];  // 16 KB
    __shared__ int    s_cnt[RPB];
    __shared__ int    s_max;

    const int cnt = g_cnt[b];
    for (int j = (tid & 63); j < cnt; j += 64)
        s_cand[r][j] = g_cand[(size_t)b * CAP + j];
    if ((tid & 63) == 0) s_cnt[r] = cnt;
    __syncthreads();
    if (tid == 0) {
        int m = 0;
        #pragma unroll
        for (int i = 0; i < RPB; i++) m = max(m, s_cnt[i]);
        s_max = m;
    }
    __syncthreads();
    const int smax = s_max;

    float a[4][4];
    #pragma unroll
    for (int c = 0; c < 4; c++)
        #pragma unroll
        for (int e = 0; e < 4; e++) a[c][e] = -INFINITY;

    // Base pointer for this thread's 16 columns (float4 units).
    const float4* Wb = (const float4*)W + h * 128 + lane;

    for (int s0 = 0; s0 < smax; s0 += 32) {
        const int jend = min(s0 + 32, cnt);
        for (int j = s0; j < jend; j++) {
            float2 e = s_cand[r][j];
            const float4* p = Wb + __float_as_int(e.y);
            const float sv = e.x;
            float4 v0 = p[0];
            float4 v1 = p[32];
            float4 v2 = p[64];
            float4 v3 = p[96];
            a[0][0] = fmaxf(a[0][0], sv + v0.x);
            a[0][1] = fmaxf(a[0][1], sv + v0.y);
            a[0][2] = fmaxf(a[0][2], sv + v0.z);
            a[0][3] = fmaxf(a[0][3], sv + v0.w);
            a[1][0] = fmaxf(a[1][0], sv + v1.x);
            a[1][1] = fmaxf(a[1][1], sv + v1.y);
            a[1][2] = fmaxf(a[1][2], sv + v1.z);
            a[1][3] = fmaxf(a[1][3], sv + v1.w);
            a[2][0] = fmaxf(a[2][0], sv + v2.x);
            a[2][1] = fmaxf(a[2][1], sv + v2.y);
            a[2][2] = fmaxf(a[2][2], sv + v2.z);
            a[2][3] = fmaxf(a[2][3], sv + v2.w);
            a[3][0] = fmaxf(a[3][0], sv + v3.x);
            a[3][1] = fmaxf(a[3][1], sv + v3.y);
            a[3][2] = fmaxf(a[3][2], sv + v3.z);
            a[3][3] = fmaxf(a[3][3], sv + v3.w);
        }
        __syncthreads();
    }

    // Certificate + (never-fires) exact fallback + tropical bias + store.
    const float* xrow = g_xn + (size_t)b * Fn;
    float* orow = out + (size_t)b * Fn;
    #pragma unroll
    for (int c = 0; c < 4; c++) {
        const int i = h * 512 + c * 128 + lane * 4;
        float4 cm = *(const float4*)(g_cmax + i);
        const float th[4] = {TAU + cm.x, TAU + cm.y, TAU + cm.z, TAU + cm.w};
        #pragma unroll
        for (int e = 0; e < 4; e++) {
            if (a[c][e] < th[e]) {
                float mfull = -INFINITY;
                const float* wc = W + (i + e);
                for (int k = 0; k < Fn; k++)
                    mfull = fmaxf(mfull, xrow[k] + wc[(size_t)k * Fn]);
                a[c][e] = mfull;
            }
        }
        float4 bb = *(const float4*)(bias + i);
        *(float4*)(orow + i) = make_float4(fmaxf(a[c][0], bb.x),
                                           fmaxf(a[c][1], bb.y),
                                           fmaxf(a[c][2], bb.z),
                                           fmaxf(a[c][3], bb.w));
    }
}

// ---------------------------------------------------------------------------
extern "C" void kernel_launch(void* const* d_in, const int* in_sizes, int n_in,
                              void* d_out, int out_size)
{
    const float* x     = (const float*)d_in[0];
    const float* W     = (const float*)d_in[1];
    const float* bvec  = (const float*)d_in[2];
    const float* gamma = (const float*)d_in[3];
    const float* beta  = (const float*)d_in[4];
    float* out = (float*)d_out;

    ln_select_kernel<<<Bn, 256>>>(x, gamma, beta);
    colmax_a<<<32, 256>>>(W);
    colmax_b<<<4, 256>>>();
    tropical_kernel<<<Bn / RPB, 512>>>(W, bvec, out);
}